// round 9
// baseline (speedup 1.0000x reference)
#include <cuda_runtime.h>
#include <cstdint>
#include <math.h>

// ---------------- constants -----------------
#define H 512
#define W 512
#define B 8
#define NPIX (B*H*W)          // 2097152

typedef unsigned long long ull;

// scratch (static device memory: allowed; no allocation)
__device__ float g_vxn[NPIX];
__device__ float g_vyn[NPIX];
__device__ float g_m0[NPIX];
__device__ float g_m1[NPIX];
__device__ int   g_list[NPIX];
__device__ int   g_count;
__device__ unsigned int g_keys[6];

// packed weights/biases, float offsets:
//  W1 @0 (4096)   W2 @4096 (2048)  WHID @6144 (256)  WRGB @6400 (96)
//  WVEL @6496 (64) B1 @6560 (64)   B2 @6624 (32)     BRGB @6656 (3)
//  BVEL @6660 (2)  BHID @6664 (8)  [pad to 7168]
#define WPACK_F 7168
__device__ float g_wpack[WPACK_F];

#define SMEM_ACT_F   16384              // 64 ch x 256 threads
#define SMEM_TOTAL_B ((SMEM_ACT_F + WPACK_F) * 4)   // 94208 bytes

// ---------------- packed f32x2 helpers -----------------
__device__ __forceinline__ ull pack2(float lo, float hi){
    ull r; asm("mov.b64 %0, {%1, %2};" : "=l"(r) : "f"(lo), "f"(hi)); return r;
}
__device__ __forceinline__ void unpack2(ull v, float& lo, float& hi){
    asm("mov.b64 {%0, %1}, %2;" : "=f"(lo), "=f"(hi) : "l"(v));
}
__device__ __forceinline__ ull ffma2(ull a, ull b, ull c){
    ull d; asm("fma.rn.f32x2 %0, %1, %2, %3;" : "=l"(d) : "l"(a), "l"(b), "l"(c)); return d;
}
__device__ __forceinline__ ull fmul2(ull a, ull b){
    ull d; asm("mul.rn.f32x2 %0, %1, %2;" : "=l"(d) : "l"(a), "l"(b)); return d;
}

// ---------------- threefry2x32 (bit-exact JAX, partitionable) -----------------
__device__ __forceinline__ uint32_t rotl32(uint32_t v, int r){ return (v<<r)|(v>>(32-r)); }

__device__ __forceinline__ void tf2x32(uint32_t k0, uint32_t k1, uint32_t x0, uint32_t x1,
                                       uint32_t& o0, uint32_t& o1){
    uint32_t k2 = k0 ^ k1 ^ 0x1BD11BDAu;
    x0 += k0; x1 += k1;
#define TFR(r) { x0 += x1; x1 = rotl32(x1,(r)); x1 ^= x0; }
    TFR(13) TFR(15) TFR(26) TFR(6)   x0 += k1; x1 += k2 + 1u;
    TFR(17) TFR(29) TFR(16) TFR(24)  x0 += k2; x1 += k0 + 2u;
    TFR(13) TFR(15) TFR(26) TFR(6)   x0 += k0; x1 += k1 + 3u;
    TFR(17) TFR(29) TFR(16) TFR(24)  x0 += k1; x1 += k2 + 4u;
    TFR(13) TFR(15) TFR(26) TFR(6)   x0 += k2; x1 += k0 + 5u;
#undef TFR
    o0 = x0; o1 = x1;
}

// partitionable random_bits: counter (0, i), output = o0 ^ o1
__device__ __forceinline__ uint32_t rng_bits(uint32_t k0, uint32_t k1, uint32_t i){
    uint32_t o0, o1;
    tf2x32(k0, k1, 0u, i, o0, o1);
    return o0 ^ o1;
}

__device__ __forceinline__ float bits_to_u01(uint32_t b){
    return __uint_as_float((b >> 9) | 0x3f800000u) - 1.0f;
}

// XLA ErfInv (f32, Giles polynomial)
__device__ __forceinline__ float erfinv32(float x){
    float w = -log1pf(-x*x);
    float p;
    if (w < 5.0f){
        w -= 2.5f;
        p = 2.81022636e-08f;
        p = fmaf(p, w, 3.43273939e-07f);
        p = fmaf(p, w, -3.5233877e-06f);
        p = fmaf(p, w, -4.39150654e-06f);
        p = fmaf(p, w, 0.00021858087f);
        p = fmaf(p, w, -0.00125372503f);
        p = fmaf(p, w, -0.00417768164f);
        p = fmaf(p, w, 0.246640727f);
        p = fmaf(p, w, 1.50140941f);
    } else {
        w = sqrtf(w) - 3.0f;
        p = -0.000200214257f;
        p = fmaf(p, w, 0.000100950558f);
        p = fmaf(p, w, 0.00134934322f);
        p = fmaf(p, w, -0.00367342844f);
        p = fmaf(p, w, 0.00573950773f);
        p = fmaf(p, w, -0.0076224613f);
        p = fmaf(p, w, 0.00943887047f);
        p = fmaf(p, w, 1.00167406f);
        p = fmaf(p, w, 2.83297682f);
    }
    return p * x;
}

// ---------------- key derivation (fold-like split, partitionable) ----------------
__global__ void key_setup(const int* __restrict__ seed){
    uint32_t K0 = 0u;
    uint32_t K1 = (uint32_t)(*seed);
    uint32_t nk0, nk1;
    tf2x32(K0, K1, 0u, 1u, nk0, nk1);
    uint32_t a0,a1,b0,b1;
    tf2x32(nk0, nk1, 0u, 0u, a0, a1);
    tf2x32(nk0, nk1, 0u, 1u, b0, b1);
    g_keys[0] = K0; g_keys[1] = K1;
    g_keys[2] = a0; g_keys[3] = a1;   // k1 (vx noise)
    g_keys[4] = b0; g_keys[5] = b1;   // k2 (vy noise)
    g_count = 0;
}

// ---------------- weight packing ----------------
__global__ void prep_weights(const float* __restrict__ w1,  const float* __restrict__ b1,
                             const float* __restrict__ w2,  const float* __restrict__ b2,
                             const float* __restrict__ wrgb,const float* __restrict__ brgb,
                             const float* __restrict__ wvel,const float* __restrict__ bvel,
                             const float* __restrict__ whid,const float* __restrict__ bhid){
    int t = threadIdx.x;
    for (int k = t; k < 4096; k += 256) g_wpack[k] = w1[k];
    for (int k = t; k < 2048; k += 256) g_wpack[4096 + k] = w2[k];
    for (int k = t; k < 256;  k += 256) g_wpack[6144 + k] = whid[k];
    if (t < 96) g_wpack[6400 + t] = wrgb[t];
    if (t < 64) g_wpack[6496 + t] = wvel[t];
    if (t < 64) g_wpack[6560 + t] = b1[t];
    if (t < 32) g_wpack[6624 + t] = b2[t];
    if (t < 3)  g_wpack[6656 + t] = brgb[t];
    if (t < 2)  g_wpack[6660 + t] = bvel[t];
    if (t < 8)  g_wpack[6664 + t] = bhid[t];
    // pad region [6672,7168) never read
}

// ---------------- kernel A: mask + noise + unfired fast path + compaction ----------------
__global__ __launch_bounds__(256)
void mask_kernel(const float* __restrict__ S, float* __restrict__ O){
    const int i    = blockIdx.x * 256 + threadIdx.x;
    const int lane = threadIdx.x & 31;

    uint32_t K0 = g_keys[0], K1 = g_keys[1];
    uint32_t A0 = g_keys[2], A1 = g_keys[3];
    uint32_t B0 = g_keys[4], B1 = g_keys[5];
    uint32_t ui = (uint32_t)i;

    float um = bits_to_u01(rng_bits(K0, K1, ui));
    int fired = (um < 0.5f);

    const float LO   = -0.99999994f;
    const float SPAN =  1.99999994f;
    float uxr = bits_to_u01(rng_bits(A0, A1, ui));
    float uyr = bits_to_u01(rng_bits(B0, B1, ui));
    float ux  = fmaxf(LO, uxr * SPAN + LO);
    float uy  = fmaxf(LO, uyr * SPAN + LO);
    float zx  = 1.41421356f * erfinv32(ux);
    float zy  = 1.41421356f * erfinv32(uy);

    const float4* S4 = (const float4*)S;
    size_t a = (size_t)i * 4;
    float4 v0 = __ldg(&S4[a+0]);
    float4 v1 = __ldg(&S4[a+1]);
    float4 v2 = __ldg(&S4[a+2]);
    float4 v3 = __ldg(&S4[a+3]);

    g_m0[i] = v0.w;

    if (fired){
        g_vxn[i] = zx;
        g_vyn[i] = zy;
    } else {
        float o0c = fminf(fmaxf(v0.x, 0.0f), 1.0f);
        float o1c = fminf(fmaxf(v0.y, 0.0f), 1.0f);
        float o2c = fminf(fmaxf(v0.z, 0.0f), 1.0f);
        float vx  = 0.95f * fminf(fmaxf(v1.x, -1.0f), 1.0f);
        float vy  = 0.95f * fminf(fmaxf(v1.y, -1.0f), 1.0f);

        float4* O4 = (float4*)O;
        size_t ob = (size_t)i * 4;
        O4[ob+0] = make_float4(o0c, o1c, o2c, v0.w);
        O4[ob+1] = make_float4(vx, vy, v1.z, v1.w);
        O4[ob+2] = v2;
        O4[ob+3] = v3;

        g_vxn[i] = vx + 0.2f * zx;
        g_vyn[i] = vy + 0.2f * zy;
    }

    unsigned bal = __ballot_sync(0xffffffffu, fired);
    int rank = __popc(bal & ((1u << lane) - 1u));
    int cnt  = __popc(bal);
    int base = 0;
    if (lane == 0 && cnt) base = atomicAdd(&g_count, cnt);
    base = __shfl_sync(0xffffffffu, base, 0);
    if (fired) g_list[base + rank] = i;
}

// ---------------- kernel B: MLP for fired pixels (weights in SMEM) ----------------
__global__ __launch_bounds__(256)
void nca_fired_kernel(const float* __restrict__ S, float* __restrict__ O){
    extern __shared__ float smem_f[];
    const int tid = threadIdx.x;
    const int count = g_count;
    if (blockIdx.x * 256 >= count) return;     // uniform block exit

    // bulk copy packed weights (28KB) into smem
    {
        const float4* src = (const float4*)g_wpack;
        float4* dst = (float4*)(smem_f + SMEM_ACT_F);
#pragma unroll
        for (int k = 0; k < 7; k++) dst[tid + 256*k] = src[tid + 256*k];
    }
    __syncthreads();
    // no barriers after this point -> per-thread early exit is safe
    const int j = blockIdx.x * 256 + tid;
    if (j >= count) return;
    const int i = g_list[j];

    float* sb = smem_f;                          // activations: 64 ch x 256
    const float* Wt   = smem_f + SMEM_ACT_F;
    const ull*  w1u   = (const ull*)(Wt);        // [c*32 + d2]
    const ull*  w2u   = (const ull*)(Wt + 4096); // [c*16 + d2]
    const ull*  whu   = (const ull*)(Wt + 6144); // [c*4 + j]
    const float* wrgb = Wt + 6400;
    const float* wvel = Wt + 6496;
    const ull*  b1u   = (const ull*)(Wt + 6560);
    const float* b2f  = Wt + 6624;
    const float* brgb = Wt + 6656;
    const float* bvel = Wt + 6660;
    const ull*  bhu   = (const ull*)(Wt + 6664);

    // ---- perception (packed f32x2) ----
    const int x = i & (W-1);
    const int y = (i >> 9) & (H-1);
    const int b = i >> 18;
    const int xm = (x-1)&(W-1), xp = (x+1)&(W-1);
    const int ym = (y-1)&(H-1), yp = (y+1)&(H-1);
    const size_t rowb = ((size_t)b) << 18;
    const float4* S4 = (const float4*)S;

#define PIXF4(yy,xx) ((rowb + (((size_t)(yy))<<9) + (size_t)(xx)) * 4)

    const ull one2  = pack2( 1.0f,  1.0f);
    const ull neg12 = pack2(-1.0f, -1.0f);
    const ull two2  = pack2( 2.0f,  2.0f);
    const ull neg22 = pack2(-2.0f, -2.0f);
    const ull neg42 = pack2(-4.0f, -4.0f);
    const ull eig2  = pack2(0.125f, 0.125f);
    const ull qtr2  = pack2(0.25f,  0.25f);

    ull pp[8], gx2[8], gy2[8], lap2[8];
    {
        size_t a = PIXF4(y,x);
#pragma unroll
        for (int q = 0; q < 4; q++){
            float4 v = __ldg(&S4[a+q]);
            pp[2*q+0] = pack2(v.x, v.y);
            pp[2*q+1] = pack2(v.z, v.w);
        }
#pragma unroll
        for (int k = 0; k < 8; k++){
            gx2[k] = 0ull; gy2[k] = 0ull;
            lap2[k] = fmul2(neg42, pp[k]);
        }
    }

#define NBRP(yy,xx,STMT) { size_t a = PIXF4(yy,xx); ull v2[8]; \
    _Pragma("unroll") for (int q = 0; q < 4; q++){ \
        float4 vv = __ldg(&S4[a+q]); \
        v2[2*q+0] = pack2(vv.x, vv.y); v2[2*q+1] = pack2(vv.z, vv.w); } \
    _Pragma("unroll") for (int k = 0; k < 8; k++){ ull v = v2[k]; STMT; } }

    NBRP(ym, xm, { gx2[k] = ffma2(neg12, v, gx2[k]); gy2[k] = ffma2(neg12, v, gy2[k]); })
    NBRP(ym, x , { gy2[k] = ffma2(neg22, v, gy2[k]); lap2[k] = ffma2(one2, v, lap2[k]); })
    NBRP(ym, xp, { gx2[k] = ffma2(one2 , v, gx2[k]); gy2[k] = ffma2(neg12, v, gy2[k]); })
    NBRP(y , xm, { gx2[k] = ffma2(neg22, v, gx2[k]); lap2[k] = ffma2(one2, v, lap2[k]); })
    NBRP(y , xp, { gx2[k] = ffma2(two2 , v, gx2[k]); lap2[k] = ffma2(one2, v, lap2[k]); })
    NBRP(yp, xm, { gx2[k] = ffma2(neg12, v, gx2[k]); gy2[k] = ffma2(one2 , v, gy2[k]); })
    NBRP(yp, x , { gy2[k] = ffma2(two2 , v, gy2[k]); lap2[k] = ffma2(one2, v, lap2[k]); })
    NBRP(yp, xp, { gx2[k] = ffma2(one2 , v, gx2[k]); gy2[k] = ffma2(one2 , v, gy2[k]); })
#undef NBRP

#pragma unroll
    for (int k = 0; k < 8; k++){
        gx2[k]  = fmul2(eig2, gx2[k]);
        gy2[k]  = fmul2(eig2, gy2[k]);
        lap2[k] = fmul2(qtr2, lap2[k]);
    }

    // spill perception (scalar column layout: conflict-free)
#pragma unroll
    for (int k = 0; k < 8; k++){
        float a0, a1;
        unpack2(pp[k],  a0, a1); sb[(2*k   )*256+tid]=a0; sb[(2*k+ 1)*256+tid]=a1;
        unpack2(gx2[k], a0, a1); sb[(16+2*k)*256+tid]=a0; sb[(17+2*k)*256+tid]=a1;
        unpack2(gy2[k], a0, a1); sb[(32+2*k)*256+tid]=a0; sb[(33+2*k)*256+tid]=a1;
        unpack2(lap2[k],a0, a1); sb[(48+2*k)*256+tid]=a0; sb[(49+2*k)*256+tid]=a1;
    }

    // ---- layer 1: h[64] = relu(p . w1 + b1), packed pairs, weights via LDS ----
    ull h2[32];
#pragma unroll
    for (int d2 = 0; d2 < 32; d2++) h2[d2] = b1u[d2];
#pragma unroll 4
    for (int c = 0; c < 64; c++){
        float pc = sb[c*256 + tid];
        ull pc2 = pack2(pc, pc);
        const ulonglong2* wrow = (const ulonglong2*)(w1u + c*32);
#pragma unroll
        for (int q = 0; q < 16; q++){
            ulonglong2 wv = wrow[q];
            h2[2*q+0] = ffma2(pc2, wv.x, h2[2*q+0]);
            h2[2*q+1] = ffma2(pc2, wv.y, h2[2*q+1]);
        }
    }
#pragma unroll
    for (int d2 = 0; d2 < 32; d2++){
        float lo, hi; unpack2(h2[d2], lo, hi);
        sb[(2*d2  )*256+tid] = fmaxf(lo, 0.0f);
        sb[(2*d2+1)*256+tid] = fmaxf(hi, 0.0f);
    }

    // ---- layer 2: xo[32] = relu(h . w2 + b2), packed pairs ----
    ull xo2[16];
    {
        const ulonglong2* b2p = (const ulonglong2*)b2f;
#pragma unroll
        for (int q = 0; q < 8; q++){
            ulonglong2 bv = b2p[q];
            xo2[2*q+0] = bv.x;
            xo2[2*q+1] = bv.y;
        }
    }
#pragma unroll 4
    for (int c = 0; c < 64; c++){
        float hc = sb[c*256 + tid];
        ull hc2 = pack2(hc, hc);
        const ulonglong2* wrow = (const ulonglong2*)(w2u + c*16);
#pragma unroll
        for (int q = 0; q < 8; q++){
            ulonglong2 wv = wrow[q];
            xo2[2*q+0] = ffma2(hc2, wv.x, xo2[2*q+0]);
            xo2[2*q+1] = ffma2(hc2, wv.y, xo2[2*q+1]);
        }
    }
    float xo[32];
#pragma unroll
    for (int d2 = 0; d2 < 16; d2++){
        float lo, hi; unpack2(xo2[d2], lo, hi);
        xo[2*d2]   = fmaxf(lo, 0.0f);
        xo[2*d2+1] = fmaxf(hi, 0.0f);
    }

    // ---- heads (hid packed, rgb/vel scalar), weights via LDS ----
    float r0 = brgb[0], r1 = brgb[1], r2 = brgb[2];
    float dvx = bvel[0], dvy = bvel[1];
    ull hid2[4];
    {
        const ulonglong2* bp = (const ulonglong2*)bhu;
        ulonglong2 bv0 = bp[0], bv1 = bp[1];
        hid2[0] = bv0.x; hid2[1] = bv0.y; hid2[2] = bv1.x; hid2[3] = bv1.y;
    }
#pragma unroll
    for (int c = 0; c < 32; c++){
        float xc = xo[c];
        ull xc2 = pack2(xc, xc);
        r0  = fmaf(xc, wrgb[c*3+0], r0);
        r1  = fmaf(xc, wrgb[c*3+1], r1);
        r2  = fmaf(xc, wrgb[c*3+2], r2);
        dvx = fmaf(xc, wvel[c*2+0], dvx);
        dvy = fmaf(xc, wvel[c*2+1], dvy);
        const ulonglong2* wh = (const ulonglong2*)(whu + c*4);
        ulonglong2 w0 = wh[0], w1v = wh[1];
        hid2[0] = ffma2(xc2, w0.x, hid2[0]);
        hid2[1] = ffma2(xc2, w0.y, hid2[1]);
        hid2[2] = ffma2(xc2, w1v.x, hid2[2]);
        hid2[3] = ffma2(xc2, w1v.y, hid2[3]);
    }
    float hid[8];
#pragma unroll
    for (int jj = 0; jj < 4; jj++) unpack2(hid2[jj], hid[2*jj], hid[2*jj+1]);

    // ---- state update (m == 1 for all pixels here) ----
    float s[16];
#pragma unroll
    for (int k = 0; k < 8; k++) unpack2(pp[k], s[2*k], s[2*k+1]);

    float o0c = fminf(fmaxf(s[0] + r0, 0.0f), 1.0f);
    float o1c = fminf(fmaxf(s[1] + r1, 0.0f), 1.0f);
    float o2c = fminf(fmaxf(s[2] + r2, 0.0f), 1.0f);
    float vx  = 0.95f * fminf(fmaxf(s[4] + dvx, -1.0f), 1.0f);
    float vy  = 0.95f * fminf(fmaxf(s[5] + dvy, -1.0f), 1.0f);

    float4* O4 = (float4*)O;
    size_t ob = (size_t)i * 4;
    O4[ob+0] = make_float4(o0c, o1c, o2c, s[3]);  // ch3 overwritten by diffuse pass
    O4[ob+1] = make_float4(vx, vy, s[6], s[7]);
    O4[ob+2] = make_float4(s[8]  + hid[0], s[9]  + hid[1],
                           s[10] + hid[2], s[11] + hid[3]);
    O4[ob+3] = make_float4(s[12] + hid[4], s[13] + hid[5],
                           s[14] + hid[6], s[15] + hid[7]);

    float zx = g_vxn[i];
    float zy = g_vyn[i];
    g_vxn[i] = vx + 0.2f * zx;
    g_vyn[i] = vy + 0.2f * zy;
}

// ---------------- advection (semi-Lagrangian, periodic bilinear) ----------------
__global__ void advect_kernel(const float* __restrict__ src, float* __restrict__ dst){
    int i = blockIdx.x * blockDim.x + threadIdx.x;
    int x = i & (W-1);
    int y = (i >> 9) & (H-1);
    int b = i >> 18;
    float vx = g_vxn[i], vy = g_vyn[i];
    float sy = (float)y - vy * 0.25f;
    float sx = (float)x - vx * 0.25f;
    float y0f = floorf(sy), x0f = floorf(sx);
    float fy = sy - y0f, fx = sx - x0f;
    int y0 = ((int)y0f) & (H-1);
    int x0 = ((int)x0f) & (W-1);
    int y1 = (y0 + 1) & (H-1);
    int x1 = (x0 + 1) & (W-1);
    int base = b << 18;
    float m00 = __ldg(&src[base + (y0<<9) + x0]);
    float m01 = __ldg(&src[base + (y0<<9) + x1]);
    float m10 = __ldg(&src[base + (y1<<9) + x0]);
    float m11 = __ldg(&src[base + (y1<<9) + x1]);
    dst[i] = (1.0f - fy) * ((1.0f - fx) * m00 + fx * m01)
           +         fy  * ((1.0f - fx) * m10 + fx * m11);
}

// ---------------- diffuse + write mass channel ----------------
__global__ void diffuse_kernel(const float* __restrict__ mb, float* __restrict__ O){
    int i = blockIdx.x * blockDim.x + threadIdx.x;
    int x = i & (W-1);
    int y = (i >> 9) & (H-1);
    int b = i >> 18;
    int xm = (x-1)&(W-1), xp = (x+1)&(W-1);
    int ym = (y-1)&(H-1), yp = (y+1)&(H-1);
    int base = b << 18;
    float mc  = mb[i];
    float avg = (__ldg(&mb[base + (y<<9)  + xp])
               + __ldg(&mb[base + (y<<9)  + xm])
               + __ldg(&mb[base + (yp<<9) + x ])
               + __ldg(&mb[base + (ym<<9) + x ])) / 4.0f;
    O[(size_t)i * 16 + 3] = mc + 0.05f * (avg - mc);
}

// ---------------- launch ----------------
extern "C" void kernel_launch(void* const* d_in, const int* in_sizes, int n_in,
                              void* d_out, int out_size){
    const float* state = (const float*)d_in[0];
    const int*   seed  = (const int*)d_in[1];

    cudaFuncSetAttribute(nca_fired_kernel,
                         cudaFuncAttributeMaxDynamicSharedMemorySize, SMEM_TOTAL_B);

    key_setup<<<1, 1>>>(seed);
    prep_weights<<<1, 256>>>((const float*)d_in[2], (const float*)d_in[3],
                             (const float*)d_in[4], (const float*)d_in[5],
                             (const float*)d_in[6], (const float*)d_in[7],
                             (const float*)d_in[8], (const float*)d_in[9],
                             (const float*)d_in[10], (const float*)d_in[11]);

    float *m0, *m1;
    cudaGetSymbolAddress((void**)&m0, g_m0);
    cudaGetSymbolAddress((void**)&m1, g_m1);

    mask_kernel<<<NPIX/256, 256>>>(state, (float*)d_out);
    nca_fired_kernel<<<NPIX/256, 256, SMEM_TOTAL_B>>>(state, (float*)d_out);
    advect_kernel<<<NPIX/256, 256>>>(m0, m1);
    advect_kernel<<<NPIX/256, 256>>>(m1, m0);
    diffuse_kernel<<<NPIX/256, 256>>>(m0, (float*)d_out);
}

// round 12
// speedup vs baseline: 1.1738x; 1.1738x over previous
#include <cuda_runtime.h>
#include <cstdint>
#include <math.h>

// ---------------- constants -----------------
#define H 512
#define W 512
#define B 8
#define NPIX (B*H*W)          // 2097152

typedef unsigned long long ull;

// scratch (static device memory: allowed; no allocation)
__device__ float g_vxn[NPIX];
__device__ float g_vyn[NPIX];
__device__ float g_m0[NPIX];
__device__ float g_m1[NPIX];
__device__ int   g_list[NPIX];
__device__ int   g_count;
__device__ unsigned int g_keys[6];

// packed weights/biases, float offsets:
//  W1 @0 (4096)   W2 @4096 (2048)  WHID @6144 (256)  WRGB @6400 (96)
//  WVEL @6496 (64) B1 @6560 (64)   B2 @6624 (32)     BRGB @6656 (3)
//  BVEL @6660 (2)  BHID @6664 (8)  [pad to 7168]
#define WPACK_F 7168
__device__ float g_wpack[WPACK_F];

#define ACT_F        32768               // 64 ch x 512 pixels
#define SMEM_TOTAL_B ((ACT_F + WPACK_F) * 4)   // 159744 bytes

// ---------------- packed f32x2 helpers -----------------
__device__ __forceinline__ ull pack2(float lo, float hi){
    ull r; asm("mov.b64 %0, {%1, %2};" : "=l"(r) : "f"(lo), "f"(hi)); return r;
}
__device__ __forceinline__ void unpack2(ull v, float& lo, float& hi){
    asm("mov.b64 {%0, %1}, %2;" : "=f"(lo), "=f"(hi) : "l"(v));
}
__device__ __forceinline__ ull ffma2(ull a, ull b, ull c){
    ull d; asm("fma.rn.f32x2 %0, %1, %2, %3;" : "=l"(d) : "l"(a), "l"(b), "l"(c)); return d;
}
__device__ __forceinline__ ull fmul2(ull a, ull b){
    ull d; asm("mul.rn.f32x2 %0, %1, %2;" : "=l"(d) : "l"(a), "l"(b)); return d;
}

// ---------------- threefry2x32 (bit-exact JAX, partitionable) -----------------
__device__ __forceinline__ uint32_t rotl32(uint32_t v, int r){ return (v<<r)|(v>>(32-r)); }

__device__ __forceinline__ void tf2x32(uint32_t k0, uint32_t k1, uint32_t x0, uint32_t x1,
                                       uint32_t& o0, uint32_t& o1){
    uint32_t k2 = k0 ^ k1 ^ 0x1BD11BDAu;
    x0 += k0; x1 += k1;
#define TFR(r) { x0 += x1; x1 = rotl32(x1,(r)); x1 ^= x0; }
    TFR(13) TFR(15) TFR(26) TFR(6)   x0 += k1; x1 += k2 + 1u;
    TFR(17) TFR(29) TFR(16) TFR(24)  x0 += k2; x1 += k0 + 2u;
    TFR(13) TFR(15) TFR(26) TFR(6)   x0 += k0; x1 += k1 + 3u;
    TFR(17) TFR(29) TFR(16) TFR(24)  x0 += k1; x1 += k2 + 4u;
    TFR(13) TFR(15) TFR(26) TFR(6)   x0 += k2; x1 += k0 + 5u;
#undef TFR
    o0 = x0; o1 = x1;
}

// partitionable random_bits: counter (0, i), output = o0 ^ o1
__device__ __forceinline__ uint32_t rng_bits(uint32_t k0, uint32_t k1, uint32_t i){
    uint32_t o0, o1;
    tf2x32(k0, k1, 0u, i, o0, o1);
    return o0 ^ o1;
}

__device__ __forceinline__ float bits_to_u01(uint32_t b){
    return __uint_as_float((b >> 9) | 0x3f800000u) - 1.0f;
}

// XLA ErfInv (f32, Giles polynomial)
__device__ __forceinline__ float erfinv32(float x){
    float w = -log1pf(-x*x);
    float p;
    if (w < 5.0f){
        w -= 2.5f;
        p = 2.81022636e-08f;
        p = fmaf(p, w, 3.43273939e-07f);
        p = fmaf(p, w, -3.5233877e-06f);
        p = fmaf(p, w, -4.39150654e-06f);
        p = fmaf(p, w, 0.00021858087f);
        p = fmaf(p, w, -0.00125372503f);
        p = fmaf(p, w, -0.00417768164f);
        p = fmaf(p, w, 0.246640727f);
        p = fmaf(p, w, 1.50140941f);
    } else {
        w = sqrtf(w) - 3.0f;
        p = -0.000200214257f;
        p = fmaf(p, w, 0.000100950558f);
        p = fmaf(p, w, 0.00134934322f);
        p = fmaf(p, w, -0.00367342844f);
        p = fmaf(p, w, 0.00573950773f);
        p = fmaf(p, w, -0.0076224613f);
        p = fmaf(p, w, 0.00943887047f);
        p = fmaf(p, w, 1.00167406f);
        p = fmaf(p, w, 2.83297682f);
    }
    return p * x;
}

// ---------------- key derivation (fold-like split, partitionable) ----------------
__global__ void key_setup(const int* __restrict__ seed){
    uint32_t K0 = 0u;
    uint32_t K1 = (uint32_t)(*seed);
    uint32_t nk0, nk1;
    tf2x32(K0, K1, 0u, 1u, nk0, nk1);
    uint32_t a0,a1,b0,b1;
    tf2x32(nk0, nk1, 0u, 0u, a0, a1);
    tf2x32(nk0, nk1, 0u, 1u, b0, b1);
    g_keys[0] = K0; g_keys[1] = K1;
    g_keys[2] = a0; g_keys[3] = a1;   // k1 (vx noise)
    g_keys[4] = b0; g_keys[5] = b1;   // k2 (vy noise)
    g_count = 0;
}

// ---------------- weight packing ----------------
__global__ void prep_weights(const float* __restrict__ w1,  const float* __restrict__ b1,
                             const float* __restrict__ w2,  const float* __restrict__ b2,
                             const float* __restrict__ wrgb,const float* __restrict__ brgb,
                             const float* __restrict__ wvel,const float* __restrict__ bvel,
                             const float* __restrict__ whid,const float* __restrict__ bhid){
    int t = threadIdx.x;
    for (int k = t; k < 4096; k += 256) g_wpack[k] = w1[k];
    for (int k = t; k < 2048; k += 256) g_wpack[4096 + k] = w2[k];
    for (int k = t; k < 256;  k += 256) g_wpack[6144 + k] = whid[k];
    if (t < 96) g_wpack[6400 + t] = wrgb[t];
    if (t < 64) g_wpack[6496 + t] = wvel[t];
    if (t < 64) g_wpack[6560 + t] = b1[t];
    if (t < 32) g_wpack[6624 + t] = b2[t];
    if (t < 3)  g_wpack[6656 + t] = brgb[t];
    if (t < 2)  g_wpack[6660 + t] = bvel[t];
    if (t < 8)  g_wpack[6664 + t] = bhid[t];
}

// ---------------- kernel A: mask + noise + unfired fast path + compaction ----------------
__global__ __launch_bounds__(256)
void mask_kernel(const float* __restrict__ S, float* __restrict__ O){
    const int i    = blockIdx.x * 256 + threadIdx.x;
    const int lane = threadIdx.x & 31;

    uint32_t K0 = g_keys[0], K1 = g_keys[1];
    uint32_t A0 = g_keys[2], A1 = g_keys[3];
    uint32_t B0 = g_keys[4], B1 = g_keys[5];
    uint32_t ui = (uint32_t)i;

    float um = bits_to_u01(rng_bits(K0, K1, ui));
    int fired = (um < 0.5f);

    const float LO   = -0.99999994f;
    const float SPAN =  1.99999994f;
    float uxr = bits_to_u01(rng_bits(A0, A1, ui));
    float uyr = bits_to_u01(rng_bits(B0, B1, ui));
    float ux  = fmaxf(LO, uxr * SPAN + LO);
    float uy  = fmaxf(LO, uyr * SPAN + LO);
    float zx  = 1.41421356f * erfinv32(ux);
    float zy  = 1.41421356f * erfinv32(uy);

    const float4* S4 = (const float4*)S;
    size_t a = (size_t)i * 4;
    float4 v0 = __ldg(&S4[a+0]);
    float4 v1 = __ldg(&S4[a+1]);
    float4 v2 = __ldg(&S4[a+2]);
    float4 v3 = __ldg(&S4[a+3]);

    g_m0[i] = v0.w;

    if (fired){
        g_vxn[i] = zx;
        g_vyn[i] = zy;
    } else {
        float o0c = fminf(fmaxf(v0.x, 0.0f), 1.0f);
        float o1c = fminf(fmaxf(v0.y, 0.0f), 1.0f);
        float o2c = fminf(fmaxf(v0.z, 0.0f), 1.0f);
        float vx  = 0.95f * fminf(fmaxf(v1.x, -1.0f), 1.0f);
        float vy  = 0.95f * fminf(fmaxf(v1.y, -1.0f), 1.0f);

        float4* O4 = (float4*)O;
        size_t ob = (size_t)i * 4;
        O4[ob+0] = make_float4(o0c, o1c, o2c, v0.w);
        O4[ob+1] = make_float4(vx, vy, v1.z, v1.w);
        O4[ob+2] = v2;
        O4[ob+3] = v3;

        g_vxn[i] = vx + 0.2f * zx;
        g_vyn[i] = vy + 0.2f * zy;
    }

    unsigned bal = __ballot_sync(0xffffffffu, fired);
    int rank = __popc(bal & ((1u << lane) - 1u));
    int cnt  = __popc(bal);
    int base = 0;
    if (lane == 0 && cnt) base = atomicAdd(&g_count, cnt);
    base = __shfl_sync(0xffffffffu, base, 0);
    if (fired) g_list[base + rank] = i;
}

// ---------------- perception: compute + spill into smem column ----------------
__device__ __forceinline__ void perceive_spill(const float* __restrict__ S,
                                               int i, float* __restrict__ sb, int col){
    const int x = i & (W-1);
    const int y = (i >> 9) & (H-1);
    const int b = i >> 18;
    const int xm = (x-1)&(W-1), xp = (x+1)&(W-1);
    const int ym = (y-1)&(H-1), yp = (y+1)&(H-1);
    const size_t rowb = ((size_t)b) << 18;
    const float4* S4 = (const float4*)S;

#define PIXF4(yy,xx) ((rowb + (((size_t)(yy))<<9) + (size_t)(xx)) * 4)

    const ull one2  = pack2( 1.0f,  1.0f);
    const ull neg12 = pack2(-1.0f, -1.0f);
    const ull two2  = pack2( 2.0f,  2.0f);
    const ull neg22 = pack2(-2.0f, -2.0f);
    const ull neg42 = pack2(-4.0f, -4.0f);
    const ull eig2  = pack2(0.125f, 0.125f);
    const ull qtr2  = pack2(0.25f,  0.25f);

    ull pp[8], gx2[8], gy2[8], lap2[8];
    {
        size_t a = PIXF4(y,x);
#pragma unroll
        for (int q = 0; q < 4; q++){
            float4 v = __ldg(&S4[a+q]);
            pp[2*q+0] = pack2(v.x, v.y);
            pp[2*q+1] = pack2(v.z, v.w);
        }
#pragma unroll
        for (int k = 0; k < 8; k++){
            gx2[k] = 0ull; gy2[k] = 0ull;
            lap2[k] = fmul2(neg42, pp[k]);
        }
    }

#define NBRP(yy,xx,STMT) { size_t a = PIXF4(yy,xx); ull v2[8]; \
    _Pragma("unroll") for (int q = 0; q < 4; q++){ \
        float4 vv = __ldg(&S4[a+q]); \
        v2[2*q+0] = pack2(vv.x, vv.y); v2[2*q+1] = pack2(vv.z, vv.w); } \
    _Pragma("unroll") for (int k = 0; k < 8; k++){ ull v = v2[k]; STMT; } }

    NBRP(ym, xm, { gx2[k] = ffma2(neg12, v, gx2[k]); gy2[k] = ffma2(neg12, v, gy2[k]); })
    NBRP(ym, x , { gy2[k] = ffma2(neg22, v, gy2[k]); lap2[k] = ffma2(one2, v, lap2[k]); })
    NBRP(ym, xp, { gx2[k] = ffma2(one2 , v, gx2[k]); gy2[k] = ffma2(neg12, v, gy2[k]); })
    NBRP(y , xm, { gx2[k] = ffma2(neg22, v, gx2[k]); lap2[k] = ffma2(one2, v, lap2[k]); })
    NBRP(y , xp, { gx2[k] = ffma2(two2 , v, gx2[k]); lap2[k] = ffma2(one2, v, lap2[k]); })
    NBRP(yp, xm, { gx2[k] = ffma2(neg12, v, gx2[k]); gy2[k] = ffma2(one2 , v, gy2[k]); })
    NBRP(yp, x , { gy2[k] = ffma2(two2 , v, gy2[k]); lap2[k] = ffma2(one2, v, lap2[k]); })
    NBRP(yp, xp, { gx2[k] = ffma2(one2 , v, gx2[k]); gy2[k] = ffma2(one2 , v, gy2[k]); })
#undef NBRP
#undef PIXF4

#pragma unroll
    for (int k = 0; k < 8; k++){
        gx2[k]  = fmul2(eig2, gx2[k]);
        gy2[k]  = fmul2(eig2, gy2[k]);
        lap2[k] = fmul2(qtr2, lap2[k]);
    }

#pragma unroll
    for (int k = 0; k < 8; k++){
        float a0, a1;
        unpack2(pp[k],  a0, a1); sb[(2*k   )*512+col]=a0; sb[(2*k+ 1)*512+col]=a1;
        unpack2(gx2[k], a0, a1); sb[(16+2*k)*512+col]=a0; sb[(17+2*k)*512+col]=a1;
        unpack2(gy2[k], a0, a1); sb[(32+2*k)*512+col]=a0; sb[(33+2*k)*512+col]=a1;
        unpack2(lap2[k],a0, a1); sb[(48+2*k)*512+col]=a0; sb[(49+2*k)*512+col]=a1;
    }
}

// ---------------- epilogue: heads tail + state write for one pixel ----------------
__device__ __forceinline__ void finish_pixel(const float* __restrict__ S, float* __restrict__ O,
                                             int i, float r0, float r1, float r2,
                                             float dvx, float dvy, const ull* hid2){
    float hid[8];
#pragma unroll
    for (int jj = 0; jj < 4; jj++) unpack2(hid2[jj], hid[2*jj], hid[2*jj+1]);

    const float4* S4 = (const float4*)S;
    size_t a = (size_t)i * 4;
    float4 s0 = __ldg(&S4[a+0]);
    float4 s1 = __ldg(&S4[a+1]);
    float4 s2 = __ldg(&S4[a+2]);
    float4 s3 = __ldg(&S4[a+3]);

    float o0c = fminf(fmaxf(s0.x + r0, 0.0f), 1.0f);
    float o1c = fminf(fmaxf(s0.y + r1, 0.0f), 1.0f);
    float o2c = fminf(fmaxf(s0.z + r2, 0.0f), 1.0f);
    float vx  = 0.95f * fminf(fmaxf(s1.x + dvx, -1.0f), 1.0f);
    float vy  = 0.95f * fminf(fmaxf(s1.y + dvy, -1.0f), 1.0f);

    float4* O4 = (float4*)O;
    size_t ob = (size_t)i * 4;
    O4[ob+0] = make_float4(o0c, o1c, o2c, s0.w);  // ch3 overwritten by diffuse pass
    O4[ob+1] = make_float4(vx, vy, s1.z, s1.w);
    O4[ob+2] = make_float4(s2.x + hid[0], s2.y + hid[1], s2.z + hid[2], s2.w + hid[3]);
    O4[ob+3] = make_float4(s3.x + hid[4], s3.y + hid[5], s3.z + hid[6], s3.w + hid[7]);

    float zx = g_vxn[i];
    float zy = g_vyn[i];
    g_vxn[i] = vx + 0.2f * zx;
    g_vyn[i] = vy + 0.2f * zy;
}

// ---------------- kernel B: MLP for fired pixels, P=2 px/thread ----------------
__global__ __launch_bounds__(256)
void nca_fired_kernel(const float* __restrict__ S, float* __restrict__ O){
    extern __shared__ float smem_f[];
    const int tid = threadIdx.x;
    const int count = g_count;
    if (blockIdx.x * 512 >= count) return;     // uniform block exit

    // bulk copy packed weights (28KB) into smem
    {
        const float4* src = (const float4*)g_wpack;
        float4* dst = (float4*)(smem_f + ACT_F);
#pragma unroll
        for (int k = 0; k < 7; k++) dst[tid + 256*k] = src[tid + 256*k];
    }
    __syncthreads();
    // no barriers after this point

    const int j0 = blockIdx.x * 512 + tid;
    const int j1 = j0 + 256;
    const bool v0 = (j0 < count);
    const bool v1 = (j1 < count);
    const int cm = count - 1;
    const int i0 = g_list[(j0 <= cm) ? j0 : cm];
    const int i1 = g_list[(j1 <= cm) ? j1 : cm];

    float* sb = smem_f;                          // activations: 64 ch x 512
    const float* Wt   = smem_f + ACT_F;
    const ull*  w1u   = (const ull*)(Wt);        // [c*32 + d2]
    const ull*  w2u   = (const ull*)(Wt + 4096); // [c*16 + d2]
    const ull*  whu   = (const ull*)(Wt + 6144); // [c*4 + j]
    const float* wrgb = Wt + 6400;
    const float* wvel = Wt + 6496;
    const ull*  b1u   = (const ull*)(Wt + 6560);
    const float* b2f  = Wt + 6624;
    const float* brgb = Wt + 6656;
    const float* bvel = Wt + 6660;
    const ull*  bhu   = (const ull*)(Wt + 6664);

    perceive_spill(S, i0, sb, tid);
    perceive_spill(S, i1, sb, tid + 256);

    // ---- layer 1: h[64] = relu(p . w1 + b1) for both pixels ----
    ull h2a[32], h2b[32];
#pragma unroll
    for (int d2 = 0; d2 < 32; d2++){ h2a[d2] = b1u[d2]; h2b[d2] = h2a[d2]; }
#pragma unroll 2
    for (int c = 0; c < 64; c++){
        float pa = sb[c*512 + tid];
        float pb = sb[c*512 + tid + 256];
        ull pa2 = pack2(pa, pa);
        ull pb2 = pack2(pb, pb);
        const ulonglong2* wrow = (const ulonglong2*)(w1u + c*32);
#pragma unroll
        for (int q = 0; q < 16; q++){
            ulonglong2 wv = wrow[q];
            h2a[2*q+0] = ffma2(pa2, wv.x, h2a[2*q+0]);
            h2a[2*q+1] = ffma2(pa2, wv.y, h2a[2*q+1]);
            h2b[2*q+0] = ffma2(pb2, wv.x, h2b[2*q+0]);
            h2b[2*q+1] = ffma2(pb2, wv.y, h2b[2*q+1]);
        }
    }
#pragma unroll
    for (int d2 = 0; d2 < 32; d2++){
        float lo, hi;
        unpack2(h2a[d2], lo, hi);
        sb[(2*d2  )*512+tid] = fmaxf(lo, 0.0f);
        sb[(2*d2+1)*512+tid] = fmaxf(hi, 0.0f);
        unpack2(h2b[d2], lo, hi);
        sb[(2*d2  )*512+tid+256] = fmaxf(lo, 0.0f);
        sb[(2*d2+1)*512+tid+256] = fmaxf(hi, 0.0f);
    }

    // ---- layer 2: xo[32] = relu(h . w2 + b2) for both pixels ----
    ull xo2a[16], xo2b[16];
    {
        const ulonglong2* b2p = (const ulonglong2*)b2f;
#pragma unroll
        for (int q = 0; q < 8; q++){
            ulonglong2 bv = b2p[q];
            xo2a[2*q+0] = bv.x; xo2a[2*q+1] = bv.y;
            xo2b[2*q+0] = bv.x; xo2b[2*q+1] = bv.y;
        }
    }
#pragma unroll 2
    for (int c = 0; c < 64; c++){
        float ha = sb[c*512 + tid];
        float hb = sb[c*512 + tid + 256];
        ull ha2 = pack2(ha, ha);
        ull hb2 = pack2(hb, hb);
        const ulonglong2* wrow = (const ulonglong2*)(w2u + c*16);
#pragma unroll
        for (int q = 0; q < 8; q++){
            ulonglong2 wv = wrow[q];
            xo2a[2*q+0] = ffma2(ha2, wv.x, xo2a[2*q+0]);
            xo2a[2*q+1] = ffma2(ha2, wv.y, xo2a[2*q+1]);
            xo2b[2*q+0] = ffma2(hb2, wv.x, xo2b[2*q+0]);
            xo2b[2*q+1] = ffma2(hb2, wv.y, xo2b[2*q+1]);
        }
    }

    // ---- heads for both pixels (relu applied inline) ----
    float r0a = brgb[0], r1a = brgb[1], r2a = brgb[2];
    float r0b = r0a, r1b = r1a, r2b = r2a;
    float dvxa = bvel[0], dvya = bvel[1];
    float dvxb = dvxa, dvyb = dvya;
    ull hid2a[4], hid2b[4];
    {
        const ulonglong2* bp = (const ulonglong2*)bhu;
        ulonglong2 bv0 = bp[0], bv1 = bp[1];
        hid2a[0] = bv0.x; hid2a[1] = bv0.y; hid2a[2] = bv1.x; hid2a[3] = bv1.y;
        hid2b[0] = bv0.x; hid2b[1] = bv0.y; hid2b[2] = bv1.x; hid2b[3] = bv1.y;
    }
#pragma unroll
    for (int c2 = 0; c2 < 16; c2++){
        float xa0, xa1, xb0, xb1;
        unpack2(xo2a[c2], xa0, xa1);
        unpack2(xo2b[c2], xb0, xb1);
        xa0 = fmaxf(xa0, 0.0f); xa1 = fmaxf(xa1, 0.0f);
        xb0 = fmaxf(xb0, 0.0f); xb1 = fmaxf(xb1, 0.0f);
#pragma unroll
        for (int u = 0; u < 2; u++){
            int c = 2*c2 + u;
            float xa = u ? xa1 : xa0;
            float xb = u ? xb1 : xb0;
            r0a  = fmaf(xa, wrgb[c*3+0], r0a);
            r1a  = fmaf(xa, wrgb[c*3+1], r1a);
            r2a  = fmaf(xa, wrgb[c*3+2], r2a);
            dvxa = fmaf(xa, wvel[c*2+0], dvxa);
            dvya = fmaf(xa, wvel[c*2+1], dvya);
            r0b  = fmaf(xb, wrgb[c*3+0], r0b);
            r1b  = fmaf(xb, wrgb[c*3+1], r1b);
            r2b  = fmaf(xb, wrgb[c*3+2], r2b);
            dvxb = fmaf(xb, wvel[c*2+0], dvxb);
            dvyb = fmaf(xb, wvel[c*2+1], dvyb);
            const ulonglong2* wh = (const ulonglong2*)(whu + c*4);
            ulonglong2 w0 = wh[0], w1v = wh[1];
            ull xa2 = pack2(xa, xa);
            ull xb2 = pack2(xb, xb);
            hid2a[0] = ffma2(xa2, w0.x,  hid2a[0]);
            hid2a[1] = ffma2(xa2, w0.y,  hid2a[1]);
            hid2a[2] = ffma2(xa2, w1v.x, hid2a[2]);
            hid2a[3] = ffma2(xa2, w1v.y, hid2a[3]);
            hid2b[0] = ffma2(xb2, w0.x,  hid2b[0]);
            hid2b[1] = ffma2(xb2, w0.y,  hid2b[1]);
            hid2b[2] = ffma2(xb2, w1v.x, hid2b[2]);
            hid2b[3] = ffma2(xb2, w1v.y, hid2b[3]);
        }
    }

    if (v0) finish_pixel(S, O, i0, r0a, r1a, r2a, dvxa, dvya, hid2a);
    if (v1) finish_pixel(S, O, i1, r0b, r1b, r2b, dvxb, dvyb, hid2b);
}

// ---------------- advection (semi-Lagrangian, periodic bilinear) ----------------
__global__ void advect_kernel(const float* __restrict__ src, float* __restrict__ dst){
    int i = blockIdx.x * blockDim.x + threadIdx.x;
    int x = i & (W-1);
    int y = (i >> 9) & (H-1);
    int b = i >> 18;
    float vx = g_vxn[i], vy = g_vyn[i];
    float sy = (float)y - vy * 0.25f;
    float sx = (float)x - vx * 0.25f;
    float y0f = floorf(sy), x0f = floorf(sx);
    float fy = sy - y0f, fx = sx - x0f;
    int y0 = ((int)y0f) & (H-1);
    int x0 = ((int)x0f) & (W-1);
    int y1 = (y0 + 1) & (H-1);
    int x1 = (x0 + 1) & (W-1);
    int base = b << 18;
    float m00 = __ldg(&src[base + (y0<<9) + x0]);
    float m01 = __ldg(&src[base + (y0<<9) + x1]);
    float m10 = __ldg(&src[base + (y1<<9) + x0]);
    float m11 = __ldg(&src[base + (y1<<9) + x1]);
    dst[i] = (1.0f - fy) * ((1.0f - fx) * m00 + fx * m01)
           +         fy  * ((1.0f - fx) * m10 + fx * m11);
}

// ---------------- diffuse + write mass channel ----------------
__global__ void diffuse_kernel(const float* __restrict__ mb, float* __restrict__ O){
    int i = blockIdx.x * blockDim.x + threadIdx.x;
    int x = i & (W-1);
    int y = (i >> 9) & (H-1);
    int b = i >> 18;
    int xm = (x-1)&(W-1), xp = (x+1)&(W-1);
    int ym = (y-1)&(H-1), yp = (y+1)&(H-1);
    int base = b << 18;
    float mc  = mb[i];
    float avg = (__ldg(&mb[base + (y<<9)  + xp])
               + __ldg(&mb[base + (y<<9)  + xm])
               + __ldg(&mb[base + (yp<<9) + x ])
               + __ldg(&mb[base + (ym<<9) + x ])) / 4.0f;
    O[(size_t)i * 16 + 3] = mc + 0.05f * (avg - mc);
}

// ---------------- launch ----------------
extern "C" void kernel_launch(void* const* d_in, const int* in_sizes, int n_in,
                              void* d_out, int out_size){
    const float* state = (const float*)d_in[0];
    const int*   seed  = (const int*)d_in[1];

    cudaFuncSetAttribute(nca_fired_kernel,
                         cudaFuncAttributeMaxDynamicSharedMemorySize, SMEM_TOTAL_B);

    key_setup<<<1, 1>>>(seed);
    prep_weights<<<1, 256>>>((const float*)d_in[2], (const float*)d_in[3],
                             (const float*)d_in[4], (const float*)d_in[5],
                             (const float*)d_in[6], (const float*)d_in[7],
                             (const float*)d_in[8], (const float*)d_in[9],
                             (const float*)d_in[10], (const float*)d_in[11]);

    float *m0, *m1;
    cudaGetSymbolAddress((void**)&m0, g_m0);
    cudaGetSymbolAddress((void**)&m1, g_m1);

    mask_kernel<<<NPIX/256, 256>>>(state, (float*)d_out);
    nca_fired_kernel<<<NPIX/512, 256, SMEM_TOTAL_B>>>(state, (float*)d_out);
    advect_kernel<<<NPIX/256, 256>>>(m0, m1);
    advect_kernel<<<NPIX/256, 256>>>(m1, m0);
    diffuse_kernel<<<NPIX/256, 256>>>(m0, (float*)d_out);
}

// round 14
// speedup vs baseline: 1.3704x; 1.1675x over previous
#include <cuda_runtime.h>
#include <cstdint>
#include <math.h>

// ---------------- constants -----------------
#define H 512
#define W 512
#define B 8
#define NPIX (B*H*W)          // 2097152

typedef unsigned long long ull;

// scratch (static device memory: allowed; no allocation)
__device__ float g_vxn[NPIX];
__device__ float g_vyn[NPIX];
__device__ float g_m0[NPIX];
__device__ float g_m1[NPIX];
__device__ int   g_list[NPIX];
__device__ int   g_count;
__device__ unsigned int g_keys[6];

// packed weights (float offsets), half-split with 16B pads for bank decorrelation:
//  W1LO @0 (2048)  pad  W1HI @2052 (2048)
//  W2LO @4100 (1024) pad W2HI @5128 (1024)
//  WHID @6152 (256)  WRGB @6408 (96)  WVEL @6504 (64)
//  B1 @6568 (64)  B2 @6632 (32)  BRGB @6664 (3)  BVEL @6667 (2)  BHID @6672 (8)
#define WPACK_F 7168
__device__ float g_wpack[WPACK_F];

#define ACT_F        16384               // 64 ch x 256 px columns
#define SMEM_TOTAL_B ((ACT_F + WPACK_F) * 4)   // 94208 bytes

// ---------------- packed f32x2 helpers -----------------
__device__ __forceinline__ ull pack2(float lo, float hi){
    ull r; asm("mov.b64 %0, {%1, %2};" : "=l"(r) : "f"(lo), "f"(hi)); return r;
}
__device__ __forceinline__ void unpack2(ull v, float& lo, float& hi){
    asm("mov.b64 {%0, %1}, %2;" : "=f"(lo), "=f"(hi) : "l"(v));
}
__device__ __forceinline__ ull ffma2(ull a, ull b, ull c){
    ull d; asm("fma.rn.f32x2 %0, %1, %2, %3;" : "=l"(d) : "l"(a), "l"(b), "l"(c)); return d;
}
__device__ __forceinline__ ull fmul2(ull a, ull b){
    ull d; asm("mul.rn.f32x2 %0, %1, %2;" : "=l"(d) : "l"(a), "l"(b)); return d;
}

// ---------------- threefry2x32 (bit-exact JAX, partitionable) -----------------
__device__ __forceinline__ uint32_t rotl32(uint32_t v, int r){ return (v<<r)|(v>>(32-r)); }

__device__ __forceinline__ void tf2x32(uint32_t k0, uint32_t k1, uint32_t x0, uint32_t x1,
                                       uint32_t& o0, uint32_t& o1){
    uint32_t k2 = k0 ^ k1 ^ 0x1BD11BDAu;
    x0 += k0; x1 += k1;
#define TFR(r) { x0 += x1; x1 = rotl32(x1,(r)); x1 ^= x0; }
    TFR(13) TFR(15) TFR(26) TFR(6)   x0 += k1; x1 += k2 + 1u;
    TFR(17) TFR(29) TFR(16) TFR(24)  x0 += k2; x1 += k0 + 2u;
    TFR(13) TFR(15) TFR(26) TFR(6)   x0 += k0; x1 += k1 + 3u;
    TFR(17) TFR(29) TFR(16) TFR(24)  x0 += k1; x1 += k2 + 4u;
    TFR(13) TFR(15) TFR(26) TFR(6)   x0 += k2; x1 += k0 + 5u;
#undef TFR
    o0 = x0; o1 = x1;
}

__device__ __forceinline__ uint32_t rng_bits(uint32_t k0, uint32_t k1, uint32_t i){
    uint32_t o0, o1;
    tf2x32(k0, k1, 0u, i, o0, o1);
    return o0 ^ o1;
}

__device__ __forceinline__ float bits_to_u01(uint32_t b){
    return __uint_as_float((b >> 9) | 0x3f800000u) - 1.0f;
}

// XLA ErfInv (f32, Giles polynomial)
__device__ __forceinline__ float erfinv32(float x){
    float w = -log1pf(-x*x);
    float p;
    if (w < 5.0f){
        w -= 2.5f;
        p = 2.81022636e-08f;
        p = fmaf(p, w, 3.43273939e-07f);
        p = fmaf(p, w, -3.5233877e-06f);
        p = fmaf(p, w, -4.39150654e-06f);
        p = fmaf(p, w, 0.00021858087f);
        p = fmaf(p, w, -0.00125372503f);
        p = fmaf(p, w, -0.00417768164f);
        p = fmaf(p, w, 0.246640727f);
        p = fmaf(p, w, 1.50140941f);
    } else {
        w = sqrtf(w) - 3.0f;
        p = -0.000200214257f;
        p = fmaf(p, w, 0.000100950558f);
        p = fmaf(p, w, 0.00134934322f);
        p = fmaf(p, w, -0.00367342844f);
        p = fmaf(p, w, 0.00573950773f);
        p = fmaf(p, w, -0.0076224613f);
        p = fmaf(p, w, 0.00943887047f);
        p = fmaf(p, w, 1.00167406f);
        p = fmaf(p, w, 2.83297682f);
    }
    return p * x;
}

// ---------------- key derivation (fold-like split, partitionable) ----------------
__global__ void key_setup(const int* __restrict__ seed){
    uint32_t K0 = 0u;
    uint32_t K1 = (uint32_t)(*seed);
    uint32_t nk0, nk1;
    tf2x32(K0, K1, 0u, 1u, nk0, nk1);
    uint32_t a0,a1,b0,b1;
    tf2x32(nk0, nk1, 0u, 0u, a0, a1);
    tf2x32(nk0, nk1, 0u, 1u, b0, b1);
    g_keys[0] = K0; g_keys[1] = K1;
    g_keys[2] = a0; g_keys[3] = a1;
    g_keys[4] = b0; g_keys[5] = b1;
    g_count = 0;
}

// ---------------- weight packing (half-split layout) ----------------
__global__ void prep_weights(const float* __restrict__ w1,  const float* __restrict__ b1,
                             const float* __restrict__ w2,  const float* __restrict__ b2,
                             const float* __restrict__ wrgb,const float* __restrict__ brgb,
                             const float* __restrict__ wvel,const float* __restrict__ bvel,
                             const float* __restrict__ whid,const float* __restrict__ bhid){
    int t = threadIdx.x;
    for (int k = t; k < 64*64; k += 256){
        int c = k >> 6, d = k & 63;
        int hf = d >> 5, dl = d & 31;
        g_wpack[(hf ? 2052 : 0) + c*32 + dl] = w1[k];
    }
    for (int k = t; k < 64*32; k += 256){
        int c = k >> 5, d = k & 31;
        int hf = d >> 4, dl = d & 15;
        g_wpack[(hf ? 5128 : 4100) + c*16 + dl] = w2[k];
    }
    for (int k = t; k < 256; k += 256) g_wpack[6152 + k] = whid[k];
    if (t < 96) g_wpack[6408 + t] = wrgb[t];
    if (t < 64) g_wpack[6504 + t] = wvel[t];
    if (t < 64) g_wpack[6568 + t] = b1[t];
    if (t < 32) g_wpack[6632 + t] = b2[t];
    if (t < 3)  g_wpack[6664 + t] = brgb[t];
    if (t < 2)  g_wpack[6667 + t] = bvel[t];
    if (t < 8)  g_wpack[6672 + t] = bhid[t];
}

// ---------------- kernel A: mask + noise + unfired fast path + compaction ----------------
__global__ __launch_bounds__(256)
void mask_kernel(const float* __restrict__ S, float* __restrict__ O){
    const int i    = blockIdx.x * 256 + threadIdx.x;
    const int lane = threadIdx.x & 31;

    uint32_t K0 = g_keys[0], K1 = g_keys[1];
    uint32_t A0 = g_keys[2], A1 = g_keys[3];
    uint32_t B0 = g_keys[4], B1 = g_keys[5];
    uint32_t ui = (uint32_t)i;

    float um = bits_to_u01(rng_bits(K0, K1, ui));
    int fired = (um < 0.5f);

    const float LO   = -0.99999994f;
    const float SPAN =  1.99999994f;
    float uxr = bits_to_u01(rng_bits(A0, A1, ui));
    float uyr = bits_to_u01(rng_bits(B0, B1, ui));
    float ux  = fmaxf(LO, uxr * SPAN + LO);
    float uy  = fmaxf(LO, uyr * SPAN + LO);
    float zx  = 1.41421356f * erfinv32(ux);
    float zy  = 1.41421356f * erfinv32(uy);

    const float4* S4 = (const float4*)S;
    size_t a = (size_t)i * 4;
    float4 v0 = __ldg(&S4[a+0]);
    float4 v1 = __ldg(&S4[a+1]);
    float4 v2 = __ldg(&S4[a+2]);
    float4 v3 = __ldg(&S4[a+3]);

    g_m0[i] = v0.w;

    if (fired){
        g_vxn[i] = zx;
        g_vyn[i] = zy;
    } else {
        float o0c = fminf(fmaxf(v0.x, 0.0f), 1.0f);
        float o1c = fminf(fmaxf(v0.y, 0.0f), 1.0f);
        float o2c = fminf(fmaxf(v0.z, 0.0f), 1.0f);
        float vx  = 0.95f * fminf(fmaxf(v1.x, -1.0f), 1.0f);
        float vy  = 0.95f * fminf(fmaxf(v1.y, -1.0f), 1.0f);

        float4* O4 = (float4*)O;
        size_t ob = (size_t)i * 4;
        O4[ob+0] = make_float4(o0c, o1c, o2c, v0.w);
        O4[ob+1] = make_float4(vx, vy, v1.z, v1.w);
        O4[ob+2] = v2;
        O4[ob+3] = v3;

        g_vxn[i] = vx + 0.2f * zx;
        g_vyn[i] = vy + 0.2f * zy;
    }

    unsigned bal = __ballot_sync(0xffffffffu, fired);
    int rank = __popc(bal & ((1u << lane) - 1u));
    int cnt  = __popc(bal);
    int base = 0;
    if (lane == 0 && cnt) base = atomicAdd(&g_count, cnt);
    base = __shfl_sync(0xffffffffu, base, 0);
    if (fired) g_list[base + rank] = i;
}

// ---------------- perception: compute + spill into smem column (stride 256) ----------------
__device__ __forceinline__ void perceive_spill(const float* __restrict__ S,
                                               int i, float* __restrict__ sb, int col){
    const int x = i & (W-1);
    const int y = (i >> 9) & (H-1);
    const int b = i >> 18;
    const int xm = (x-1)&(W-1), xp = (x+1)&(W-1);
    const int ym = (y-1)&(H-1), yp = (y+1)&(H-1);
    const size_t rowb = ((size_t)b) << 18;
    const float4* S4 = (const float4*)S;

#define PIXF4(yy,xx) ((rowb + (((size_t)(yy))<<9) + (size_t)(xx)) * 4)

    const ull one2  = pack2( 1.0f,  1.0f);
    const ull neg12 = pack2(-1.0f, -1.0f);
    const ull two2  = pack2( 2.0f,  2.0f);
    const ull neg22 = pack2(-2.0f, -2.0f);
    const ull neg42 = pack2(-4.0f, -4.0f);
    const ull eig2  = pack2(0.125f, 0.125f);
    const ull qtr2  = pack2(0.25f,  0.25f);

    ull pp[8], gx2[8], gy2[8], lap2[8];
    {
        size_t a = PIXF4(y,x);
#pragma unroll
        for (int q = 0; q < 4; q++){
            float4 v = __ldg(&S4[a+q]);
            pp[2*q+0] = pack2(v.x, v.y);
            pp[2*q+1] = pack2(v.z, v.w);
        }
#pragma unroll
        for (int k = 0; k < 8; k++){
            gx2[k] = 0ull; gy2[k] = 0ull;
            lap2[k] = fmul2(neg42, pp[k]);
        }
    }

#define NBRP(yy,xx,STMT) { size_t a = PIXF4(yy,xx); ull v2[8]; \
    _Pragma("unroll") for (int q = 0; q < 4; q++){ \
        float4 vv = __ldg(&S4[a+q]); \
        v2[2*q+0] = pack2(vv.x, vv.y); v2[2*q+1] = pack2(vv.z, vv.w); } \
    _Pragma("unroll") for (int k = 0; k < 8; k++){ ull v = v2[k]; STMT; } }

    NBRP(ym, xm, { gx2[k] = ffma2(neg12, v, gx2[k]); gy2[k] = ffma2(neg12, v, gy2[k]); })
    NBRP(ym, x , { gy2[k] = ffma2(neg22, v, gy2[k]); lap2[k] = ffma2(one2, v, lap2[k]); })
    NBRP(ym, xp, { gx2[k] = ffma2(one2 , v, gx2[k]); gy2[k] = ffma2(neg12, v, gy2[k]); })
    NBRP(y , xm, { gx2[k] = ffma2(neg22, v, gx2[k]); lap2[k] = ffma2(one2, v, lap2[k]); })
    NBRP(y , xp, { gx2[k] = ffma2(two2 , v, gx2[k]); lap2[k] = ffma2(one2, v, lap2[k]); })
    NBRP(yp, xm, { gx2[k] = ffma2(neg12, v, gx2[k]); gy2[k] = ffma2(one2 , v, gy2[k]); })
    NBRP(yp, x , { gy2[k] = ffma2(two2 , v, gy2[k]); lap2[k] = ffma2(one2, v, lap2[k]); })
    NBRP(yp, xp, { gx2[k] = ffma2(one2 , v, gx2[k]); gy2[k] = ffma2(one2 , v, gy2[k]); })
#undef NBRP
#undef PIXF4

#pragma unroll
    for (int k = 0; k < 8; k++){
        gx2[k]  = fmul2(eig2, gx2[k]);
        gy2[k]  = fmul2(eig2, gy2[k]);
        lap2[k] = fmul2(qtr2, lap2[k]);
    }

#pragma unroll
    for (int k = 0; k < 8; k++){
        float a0, a1;
        unpack2(pp[k],  a0, a1); sb[(2*k   )*256+col]=a0; sb[(2*k+ 1)*256+col]=a1;
        unpack2(gx2[k], a0, a1); sb[(16+2*k)*256+col]=a0; sb[(17+2*k)*256+col]=a1;
        unpack2(gy2[k], a0, a1); sb[(32+2*k)*256+col]=a0; sb[(33+2*k)*256+col]=a1;
        unpack2(lap2[k],a0, a1); sb[(48+2*k)*256+col]=a0; sb[(49+2*k)*256+col]=a1;
    }
}

// ---------------- epilogue: heads tail + state write for one pixel ----------------
__device__ __forceinline__ void finish_pixel(const float* __restrict__ S, float* __restrict__ O,
                                             int i, float r0, float r1, float r2,
                                             float dvx, float dvy, const ull* hid2){
    float hid[8];
#pragma unroll
    for (int jj = 0; jj < 4; jj++) unpack2(hid2[jj], hid[2*jj], hid[2*jj+1]);

    const float4* S4 = (const float4*)S;
    size_t a = (size_t)i * 4;
    float4 s0 = __ldg(&S4[a+0]);
    float4 s1 = __ldg(&S4[a+1]);
    float4 s2 = __ldg(&S4[a+2]);
    float4 s3 = __ldg(&S4[a+3]);

    float o0c = fminf(fmaxf(s0.x + r0, 0.0f), 1.0f);
    float o1c = fminf(fmaxf(s0.y + r1, 0.0f), 1.0f);
    float o2c = fminf(fmaxf(s0.z + r2, 0.0f), 1.0f);
    float vx  = 0.95f * fminf(fmaxf(s1.x + dvx, -1.0f), 1.0f);
    float vy  = 0.95f * fminf(fmaxf(s1.y + dvy, -1.0f), 1.0f);

    float4* O4 = (float4*)O;
    size_t ob = (size_t)i * 4;
    O4[ob+0] = make_float4(o0c, o1c, o2c, s0.w);  // ch3 overwritten by diffuse pass
    O4[ob+1] = make_float4(vx, vy, s1.z, s1.w);
    O4[ob+2] = make_float4(s2.x + hid[0], s2.y + hid[1], s2.z + hid[2], s2.w + hid[3]);
    O4[ob+3] = make_float4(s3.x + hid[4], s3.y + hid[5], s3.z + hid[6], s3.w + hid[7]);

    float zx = g_vxn[i];
    float zy = g_vyn[i];
    g_vxn[i] = vx + 0.2f * zx;
    g_vyn[i] = vy + 0.2f * zy;
}

// ---------------- kernel B: output-split lane pairs, 4 px per pair ----------------
__global__ __launch_bounds__(128, 2)
void nca_fired_kernel(const float* __restrict__ S, float* __restrict__ O){
    extern __shared__ float smem_f[];
    const int tid = threadIdx.x;
    const int count = g_count;
    if (blockIdx.x * 256 >= count) return;     // uniform block exit (handles count==0)

    // bulk copy packed weights (28KB) into smem
    {
        const float4* src = (const float4*)g_wpack;
        float4* dst = (float4*)(smem_f + ACT_F);
#pragma unroll
        for (int k = 0; k < 14; k++) dst[tid + 128*k] = src[tid + 128*k];
    }
    __syncthreads();

    const int half   = tid & 1;          // output half: 0 -> d 0..31, 1 -> d 32..63
    const int pairId = tid >> 1;         // 0..63
    const int colb   = pairId * 4;       // act column base for this pair's 4 px
    const int cm     = count - 1;
    const int jb     = blockIdx.x * 256 + pairId * 4;

    // this lane's 2 target pixels (for perception + epilogue)
    const int qa = half * 2, qb = qa + 1;
    int ja = jb + qa, jbn = jb + qb;
    bool va = (ja < count), vb = (jbn < count);
    int ia = g_list[ja <= cm ? ja : cm];
    int ib = g_list[jbn <= cm ? jbn : cm];

    float* sb = smem_f;
    const float* Wt = smem_f + ACT_F;

    perceive_spill(S, ia, sb, colb + qa);
    perceive_spill(S, ib, sb, colb + qb);
    __syncwarp();

    // ---- layer 1: acc[q][d2] = outputs (half*32+2d2, +1) for pixel q ----
    ull acc[4][16];
    {
        const ull* b1u = (const ull*)(Wt + 6568);
#pragma unroll
        for (int d = 0; d < 16; d++){
            ull bv = b1u[half*16 + d];
            acc[0][d]=bv; acc[1][d]=bv; acc[2][d]=bv; acc[3][d]=bv;
        }
    }
    {
        const ulonglong2* w1L = (const ulonglong2*)(Wt + (half ? 2052 : 0));
#pragma unroll 2
        for (int c = 0; c < 64; c++){
            float4 pv = *(const float4*)&sb[c*256 + colb];
            ull p0 = pack2(pv.x, pv.x), p1 = pack2(pv.y, pv.y);
            ull p2 = pack2(pv.z, pv.z), p3 = pack2(pv.w, pv.w);
            const ulonglong2* wrow = w1L + c*8;
#pragma unroll
            for (int qq = 0; qq < 8; qq++){
                ulonglong2 wv = wrow[qq];
                acc[0][2*qq+0]=ffma2(p0,wv.x,acc[0][2*qq+0]); acc[0][2*qq+1]=ffma2(p0,wv.y,acc[0][2*qq+1]);
                acc[1][2*qq+0]=ffma2(p1,wv.x,acc[1][2*qq+0]); acc[1][2*qq+1]=ffma2(p1,wv.y,acc[1][2*qq+1]);
                acc[2][2*qq+0]=ffma2(p2,wv.x,acc[2][2*qq+0]); acc[2][2*qq+1]=ffma2(p2,wv.y,acc[2][2*qq+1]);
                acc[3][2*qq+0]=ffma2(p3,wv.x,acc[3][2*qq+0]); acc[3][2*qq+1]=ffma2(p3,wv.y,acc[3][2*qq+1]);
            }
        }
    }
    // relu + store h rows (lane's half rows, its pair's 4 columns)
#pragma unroll
    for (int d = 0; d < 16; d++){
        float a0,a1,b0,b1,c0,c1,e0,e1;
        unpack2(acc[0][d], a0, a1); unpack2(acc[1][d], b0, b1);
        unpack2(acc[2][d], c0, c1); unpack2(acc[3][d], e0, e1);
        int r0 = half*32 + 2*d, r1 = r0 + 1;
        *(float4*)&sb[r0*256 + colb] = make_float4(fmaxf(a0,0.f), fmaxf(b0,0.f), fmaxf(c0,0.f), fmaxf(e0,0.f));
        *(float4*)&sb[r1*256 + colb] = make_float4(fmaxf(a1,0.f), fmaxf(b1,0.f), fmaxf(c1,0.f), fmaxf(e1,0.f));
    }
    __syncwarp();

    // ---- layer 2: xacc[q][t] = outputs (half*16+2t, +1) for pixel q ----
    ull xacc[4][8];
    {
        const ull* b2u = (const ull*)(Wt + 6632);
#pragma unroll
        for (int t = 0; t < 8; t++){
            ull bv = b2u[half*8 + t];
            xacc[0][t]=bv; xacc[1][t]=bv; xacc[2][t]=bv; xacc[3][t]=bv;
        }
    }
    {
        const ulonglong2* w2L = (const ulonglong2*)(Wt + (half ? 5128 : 4100));
#pragma unroll 2
        for (int c = 0; c < 64; c++){
            float4 hv = *(const float4*)&sb[c*256 + colb];
            ull p0 = pack2(hv.x, hv.x), p1 = pack2(hv.y, hv.y);
            ull p2 = pack2(hv.z, hv.z), p3 = pack2(hv.w, hv.w);
            const ulonglong2* wrow = w2L + c*4;
#pragma unroll
            for (int qq = 0; qq < 4; qq++){
                ulonglong2 wv = wrow[qq];
                xacc[0][2*qq+0]=ffma2(p0,wv.x,xacc[0][2*qq+0]); xacc[0][2*qq+1]=ffma2(p0,wv.y,xacc[0][2*qq+1]);
                xacc[1][2*qq+0]=ffma2(p1,wv.x,xacc[1][2*qq+0]); xacc[1][2*qq+1]=ffma2(p1,wv.y,xacc[1][2*qq+1]);
                xacc[2][2*qq+0]=ffma2(p2,wv.x,xacc[2][2*qq+0]); xacc[2][2*qq+1]=ffma2(p2,wv.y,xacc[2][2*qq+1]);
                xacc[3][2*qq+0]=ffma2(p3,wv.x,xacc[3][2*qq+0]); xacc[3][2*qq+1]=ffma2(p3,wv.y,xacc[3][2*qq+1]);
            }
        }
    }

    // ---- exchange xo halves within the lane pair (pre-relu) ----
    // even lane ends with full xo for pixels q0,q1; odd lane for q2,q3.
    ull xo2a[16], xo2b[16];
#pragma unroll
    for (int t = 0; t < 8; t++){
        ull sA = half ? xacc[0][t] : xacc[2][t];   // give partner its pixel-qa data
        ull sB = half ? xacc[1][t] : xacc[3][t];   // give partner its pixel-qb data
        ull rA = __shfl_xor_sync(0xffffffffu, sA, 1);
        ull rB = __shfl_xor_sync(0xffffffffu, sB, 1);
        if (half == 0){
            xo2a[t]   = xacc[0][t];  xo2a[8+t] = rA;   // px q0: lo own, hi recv
            xo2b[t]   = xacc[1][t];  xo2b[8+t] = rB;   // px q1
        } else {
            xo2a[t]   = rA;          xo2a[8+t] = xacc[2][t];   // px q2: lo recv, hi own
            xo2b[t]   = rB;          xo2b[8+t] = xacc[3][t];   // px q3
        }
    }

    // ---- heads for the lane's 2 pixels (relu applied inline) ----
    const ull*  whu   = (const ull*)(Wt + 6152);
    const float* wrgb = Wt + 6408;
    const float* wvel = Wt + 6504;
    const float* brgb = Wt + 6664;
    const float* bvel = Wt + 6667;
    const ull*  bhu   = (const ull*)(Wt + 6672);

    float r0a = brgb[0], r1a = brgb[1], r2a = brgb[2];
    float r0b = r0a, r1b = r1a, r2b = r2a;
    float dvxa = bvel[0], dvya = bvel[1];
    float dvxb = dvxa, dvyb = dvya;
    ull hid2a[4], hid2b[4];
    {
        const ulonglong2* bp = (const ulonglong2*)bhu;
        ulonglong2 bv0 = bp[0], bv1 = bp[1];
        hid2a[0] = bv0.x; hid2a[1] = bv0.y; hid2a[2] = bv1.x; hid2a[3] = bv1.y;
        hid2b[0] = bv0.x; hid2b[1] = bv0.y; hid2b[2] = bv1.x; hid2b[3] = bv1.y;
    }
#pragma unroll
    for (int c2 = 0; c2 < 16; c2++){
        float xa0, xa1, xb0, xb1;
        unpack2(xo2a[c2], xa0, xa1);
        unpack2(xo2b[c2], xb0, xb1);
        xa0 = fmaxf(xa0, 0.0f); xa1 = fmaxf(xa1, 0.0f);
        xb0 = fmaxf(xb0, 0.0f); xb1 = fmaxf(xb1, 0.0f);
#pragma unroll
        for (int u = 0; u < 2; u++){
            int c = 2*c2 + u;
            float xa = u ? xa1 : xa0;
            float xb = u ? xb1 : xb0;
            r0a  = fmaf(xa, wrgb[c*3+0], r0a);
            r1a  = fmaf(xa, wrgb[c*3+1], r1a);
            r2a  = fmaf(xa, wrgb[c*3+2], r2a);
            dvxa = fmaf(xa, wvel[c*2+0], dvxa);
            dvya = fmaf(xa, wvel[c*2+1], dvya);
            r0b  = fmaf(xb, wrgb[c*3+0], r0b);
            r1b  = fmaf(xb, wrgb[c*3+1], r1b);
            r2b  = fmaf(xb, wrgb[c*3+2], r2b);
            dvxb = fmaf(xb, wvel[c*2+0], dvxb);
            dvyb = fmaf(xb, wvel[c*2+1], dvyb);
            const ulonglong2* wh = (const ulonglong2*)(whu + c*4);
            ulonglong2 w0 = wh[0], w1v = wh[1];
            ull xa2 = pack2(xa, xa);
            ull xb2 = pack2(xb, xb);
            hid2a[0] = ffma2(xa2, w0.x,  hid2a[0]);
            hid2a[1] = ffma2(xa2, w0.y,  hid2a[1]);
            hid2a[2] = ffma2(xa2, w1v.x, hid2a[2]);
            hid2a[3] = ffma2(xa2, w1v.y, hid2a[3]);
            hid2b[0] = ffma2(xb2, w0.x,  hid2b[0]);
            hid2b[1] = ffma2(xb2, w0.y,  hid2b[1]);
            hid2b[2] = ffma2(xb2, w1v.x, hid2b[2]);
            hid2b[3] = ffma2(xb2, w1v.y, hid2b[3]);
        }
    }

    if (va) finish_pixel(S, O, ia, r0a, r1a, r2a, dvxa, dvya, hid2a);
    if (vb) finish_pixel(S, O, ib, r0b, r1b, r2b, dvxb, dvyb, hid2b);
}

// ---------------- advection (semi-Lagrangian, periodic bilinear) ----------------
__global__ void advect_kernel(const float* __restrict__ src, float* __restrict__ dst){
    int i = blockIdx.x * blockDim.x + threadIdx.x;
    int x = i & (W-1);
    int y = (i >> 9) & (H-1);
    int b = i >> 18;
    float vx = g_vxn[i], vy = g_vyn[i];
    float sy = (float)y - vy * 0.25f;
    float sx = (float)x - vx * 0.25f;
    float y0f = floorf(sy), x0f = floorf(sx);
    float fy = sy - y0f, fx = sx - x0f;
    int y0 = ((int)y0f) & (H-1);
    int x0 = ((int)x0f) & (W-1);
    int y1 = (y0 + 1) & (H-1);
    int x1 = (x0 + 1) & (W-1);
    int base = b << 18;
    float m00 = __ldg(&src[base + (y0<<9) + x0]);
    float m01 = __ldg(&src[base + (y0<<9) + x1]);
    float m10 = __ldg(&src[base + (y1<<9) + x0]);
    float m11 = __ldg(&src[base + (y1<<9) + x1]);
    dst[i] = (1.0f - fy) * ((1.0f - fx) * m00 + fx * m01)
           +         fy  * ((1.0f - fx) * m10 + fx * m11);
}

// ---------------- diffuse + write mass channel ----------------
__global__ void diffuse_kernel(const float* __restrict__ mb, float* __restrict__ O){
    int i = blockIdx.x * blockDim.x + threadIdx.x;
    int x = i & (W-1);
    int y = (i >> 9) & (H-1);
    int b = i >> 18;
    int xm = (x-1)&(W-1), xp = (x+1)&(W-1);
    int ym = (y-1)&(H-1), yp = (y+1)&(H-1);
    int base = b << 18;
    float mc  = mb[i];
    float avg = (__ldg(&mb[base + (y<<9)  + xp])
               + __ldg(&mb[base + (y<<9)  + xm])
               + __ldg(&mb[base + (yp<<9) + x ])
               + __ldg(&mb[base + (ym<<9) + x ])) / 4.0f;
    O[(size_t)i * 16 + 3] = mc + 0.05f * (avg - mc);
}

// ---------------- launch ----------------
extern "C" void kernel_launch(void* const* d_in, const int* in_sizes, int n_in,
                              void* d_out, int out_size){
    const float* state = (const float*)d_in[0];
    const int*   seed  = (const int*)d_in[1];

    cudaFuncSetAttribute(nca_fired_kernel,
                         cudaFuncAttributeMaxDynamicSharedMemorySize, SMEM_TOTAL_B);

    key_setup<<<1, 1>>>(seed);
    prep_weights<<<1, 256>>>((const float*)d_in[2], (const float*)d_in[3],
                             (const float*)d_in[4], (const float*)d_in[5],
                             (const float*)d_in[6], (const float*)d_in[7],
                             (const float*)d_in[8], (const float*)d_in[9],
                             (const float*)d_in[10], (const float*)d_in[11]);

    float *m0, *m1;
    cudaGetSymbolAddress((void**)&m0, g_m0);
    cudaGetSymbolAddress((void**)&m1, g_m1);

    mask_kernel<<<NPIX/256, 256>>>(state, (float*)d_out);
    nca_fired_kernel<<<NPIX/256, 128, SMEM_TOTAL_B>>>(state, (float*)d_out);
    advect_kernel<<<NPIX/256, 256>>>(m0, m1);
    advect_kernel<<<NPIX/256, 256>>>(m1, m0);
    diffuse_kernel<<<NPIX/256, 256>>>(m0, (float*)d_out);
}